// round 3
// baseline (speedup 1.0000x reference)
#include <cuda_runtime.h>
#include <cstdint>
#include <cstddef>

#define S_LEN   2048
#define BATCH   32
#define HID     256
#define GRID_REC 128

// ---------------- device scratch (no allocations allowed) ----------------
__device__ float g_Xc[(size_t)65536 * 1024];   // [s][col][b] : 256 MB, x@Wx + b
__device__ float g_hbuf[2][BATCH * HID];       // [k][b] layout, double buffered
__device__ unsigned g_bar_count;
__device__ volatile unsigned g_bar_epoch;

// ---------------- activations (accurate fast paths) ----------------
__device__ __forceinline__ float fsigm(float x) {
    return 1.0f / (1.0f + __expf(-x));
}
__device__ __forceinline__ float ftanh(float x) {
    x = fminf(9.0f, fmaxf(-9.0f, x));
    float e = __expf(-2.0f * x);
    return __fdividef(1.0f - e, 1.0f + e);
}

// ---------------- phase 1: Xc[s][col][b] = x[b][s][:] @ W[:256][col] + bias[col] ----------------
// M = 65536 rows ordered r = s*32 + b ; N = 1024 ; K = 256
__global__ void __launch_bounds__(256) gemm_x_kernel(const float* __restrict__ x,
                                                     const float* __restrict__ W,
                                                     const float* __restrict__ bias) {
    __shared__ float As[8][132];   // k-major, padded (conflict-free)
    __shared__ float Bs[8][128];
    const int tid = threadIdx.x;
    const int rt = blockIdx.x, ct = blockIdx.y;

    const int a_ri = tid >> 1, a_kq = (tid & 1) << 2;
    const int row  = rt * 128 + a_ri;            // r = s*32 + b
    const float* a_src = x + (size_t)(row & 31) * (S_LEN * 256)
                           + (size_t)(row >> 5) * 256 + a_kq;
    const int b_kr = tid >> 5, b_c4 = (tid & 31) << 2;
    const float* b_src = W + (size_t)b_kr * 1024 + ct * 128 + b_c4;

    const int ry = tid >> 4, cx = tid & 15;
    float acc[8][8];
#pragma unroll
    for (int i = 0; i < 8; i++)
#pragma unroll
        for (int j = 0; j < 8; j++) acc[i][j] = 0.0f;

    for (int kb = 0; kb < 256; kb += 8) {
        float4 av = *(const float4*)(a_src + kb);
        float4 bv = *(const float4*)(b_src + (size_t)kb * 1024);
        __syncthreads();
        As[a_kq + 0][a_ri] = av.x;
        As[a_kq + 1][a_ri] = av.y;
        As[a_kq + 2][a_ri] = av.z;
        As[a_kq + 3][a_ri] = av.w;
        *(float4*)&Bs[b_kr][b_c4] = bv;
        __syncthreads();
#pragma unroll
        for (int k = 0; k < 8; k++) {
            float ar[8], br[8];
            *(float4*)(ar)     = *(const float4*)&As[k][ry * 8];
            *(float4*)(ar + 4) = *(const float4*)&As[k][ry * 8 + 4];
            *(float4*)(br)     = *(const float4*)&Bs[k][cx * 8];
            *(float4*)(br + 4) = *(const float4*)&Bs[k][cx * 8 + 4];
#pragma unroll
            for (int i = 0; i < 8; i++)
#pragma unroll
                for (int j = 0; j < 8; j++)
                    acc[i][j] = fmaf(ar[i], br[j], acc[i][j]);
        }
    }

    float bb[8];
#pragma unroll
    for (int j = 0; j < 8; j++) bb[j] = bias[ct * 128 + cx * 8 + j];

#pragma unroll
    for (int i = 0; i < 8; i++) {
        int r = rt * 128 + ry * 8 + i;
        size_t base = (size_t)(r >> 5) * 32768 + (size_t)(r & 31);
#pragma unroll
        for (int j = 0; j < 8; j++) {
            int col = ct * 128 + cx * 8 + j;
            g_Xc[base + (size_t)col * 32] = acc[i][j] + bb[j];
        }
    }
}

// ---------------- init: barrier reset, h0 transpose, zero output tail ----------------
__global__ void init_kernel(const float* __restrict__ h0, float* __restrict__ out) {
    int t = blockIdx.x * blockDim.x + threadIdx.x;   // 16*256 = 4096 threads
    if (t == 0) { g_bar_count = 0; g_bar_epoch = 0; }
    for (int idx = t; idx < BATCH * HID; idx += 4096)
        g_hbuf[0][idx] = h0[(idx & 31) * HID + (idx >> 5)];     // [k][b] <- [b][k]
    float* tail = out + (size_t)BATCH * S_LEN * HID;            // the two zero tensors
    for (int idx = t; idx < 2 * BATCH * HID; idx += 4096) tail[idx] = 0.0f;
}

// ---------------- grid-wide barrier (all 128 CTAs co-resident) ----------------
__device__ __forceinline__ void grid_barrier(int step) {
    __threadfence();
    __syncthreads();
    if (threadIdx.x == 0) {
        unsigned arrived = atomicAdd(&g_bar_count, 1u) + 1u;
        if (arrived == (unsigned)GRID_REC * (unsigned)(step + 1)) {
            atomicExch((unsigned*)&g_bar_epoch, (unsigned)(step + 1));
        } else {
            while (g_bar_epoch < (unsigned)(step + 1)) { }
        }
        __threadfence();
    }
    __syncthreads();
}

// ---------------- phase 2: persistent recurrence ----------------
// CTA cb owns hidden units n in {2cb, 2cb+1} for all 32 batches.
// Thread t: b = t&31, slot = t>>5 ; slot -> (nl = slot&1, kseg = slot>>1).
// Each thread: 4 gate dot-products over its 64-k segment; smem reduce; owners (t<64) update c,h.
__global__ void __launch_bounds__(256, 1) lstm_rec_kernel(const float* __restrict__ W,
                                                          const float* __restrict__ c0,
                                                          float* __restrict__ out) {
    __shared__ float h_s[BATCH * HID];     // [k][b]  32 KB
    __shared__ float Wsh[8][256];          // [nl*4+g][k]  8 KB (weight-stationary)
    __shared__ float red[4][2][4][32];     // [kseg][nl][gate][b]  4 KB

    const int tid = threadIdx.x;
    const int cb = blockIdx.x;
    const int n_base = cb * 2;

    // one-time Wh load: Wsh[nl*4+g][k] = W[256+k][g*256 + n_base + nl]
    for (int idx = tid; idx < 2048; idx += 256) {
        int cl = idx >> 8, k = idx & 255;
        Wsh[cl][k] = W[(size_t)(256 + k) * 1024 + (cl & 3) * 256 + n_base + (cl >> 2)];
    }

    const int b  = tid & 31;
    const int slot = tid >> 5;
    const int nl = slot & 1;
    const int ks = slot >> 1;
    const int k0 = ks * 64;

    const bool owner = (tid < 64);
    const int o_b = tid & 31;
    const int o_nl = (tid >> 5) & 1;
    const int o_n = n_base + o_nl;
    float c_reg = 0.0f;
    if (owner) c_reg = c0[o_b * HID + o_n];
    __syncthreads();

    const float* w0p = &Wsh[nl * 4 + 0][k0];
    const float* w1p = &Wsh[nl * 4 + 1][k0];
    const float* w2p = &Wsh[nl * 4 + 2][k0];
    const float* w3p = &Wsh[nl * 4 + 3][k0];
    const float* hp  = &h_s[k0 * 32 + b];

    for (int s = 0; s < S_LEN; s++) {
        const float* hsrc = g_hbuf[s & 1];
        float* hdst = g_hbuf[(s & 1) ^ 1];

        // prefetch this step's Xc early (DRAM latency hidden under compute)
        float xcv0 = 0.f, xcv1 = 0.f, xcv2 = 0.f, xcv3 = 0.f;
        if (owner) {
            const float* xp = g_Xc + (size_t)s * 32768 + o_n * 32 + o_b;
            xcv0 = xp[0];
            xcv1 = xp[8192];
            xcv2 = xp[16384];
            xcv3 = xp[24576];
        }

        // load h into smem (coalesced float4 copy; layouts identical)
        {
            float4* d4 = (float4*)h_s;
            const float4* s4 = (const float4*)hsrc;
#pragma unroll
            for (int j = 0; j < 8; j++) d4[tid + 256 * j] = s4[tid + 256 * j];
        }
        __syncthreads();

        // 4 gate dot-products over this thread's 64-k segment
        float a0 = 0.f, a1 = 0.f, a2 = 0.f, a3 = 0.f;
#pragma unroll
        for (int kk = 0; kk < 64; kk += 4) {
            float4 w0 = *(const float4*)(w0p + kk);   // broadcast LDS.128
            float4 w1 = *(const float4*)(w1p + kk);
            float4 w2 = *(const float4*)(w2p + kk);
            float4 w3 = *(const float4*)(w3p + kk);
            float h0v = hp[kk * 32];
            float h1v = hp[kk * 32 + 32];
            float h2v = hp[kk * 32 + 64];
            float h3v = hp[kk * 32 + 96];
            a0 = fmaf(h0v, w0.x, a0); a0 = fmaf(h1v, w0.y, a0); a0 = fmaf(h2v, w0.z, a0); a0 = fmaf(h3v, w0.w, a0);
            a1 = fmaf(h0v, w1.x, a1); a1 = fmaf(h1v, w1.y, a1); a1 = fmaf(h2v, w1.z, a1); a1 = fmaf(h3v, w1.w, a1);
            a2 = fmaf(h0v, w2.x, a2); a2 = fmaf(h1v, w2.y, a2); a2 = fmaf(h2v, w2.z, a2); a2 = fmaf(h3v, w2.w, a2);
            a3 = fmaf(h0v, w3.x, a3); a3 = fmaf(h1v, w3.y, a3); a3 = fmaf(h2v, w3.z, a3); a3 = fmaf(h3v, w3.w, a3);
        }
        red[ks][nl][0][b] = a0;
        red[ks][nl][1][b] = a1;
        red[ks][nl][2][b] = a2;
        red[ks][nl][3][b] = a3;
        __syncthreads();

        if (owner) {
            float z0 = red[0][o_nl][0][o_b] + red[1][o_nl][0][o_b] + red[2][o_nl][0][o_b] + red[3][o_nl][0][o_b] + xcv0;
            float z1 = red[0][o_nl][1][o_b] + red[1][o_nl][1][o_b] + red[2][o_nl][1][o_b] + red[3][o_nl][1][o_b] + xcv1;
            float z2 = red[0][o_nl][2][o_b] + red[1][o_nl][2][o_b] + red[2][o_nl][2][o_b] + red[3][o_nl][2][o_b] + xcv2;
            float z3 = red[0][o_nl][3][o_b] + red[1][o_nl][3][o_b] + red[2][o_nl][3][o_b] + red[3][o_nl][3][o_b] + xcv3;
            // full pre-activation goes through tanh first (reference quirk)
            z0 = ftanh(z0); z1 = ftanh(z1); z2 = ftanh(z2); z3 = ftanh(z3);
            float ig = fsigm(z0);
            float fg = fsigm(z1);
            float gg = ftanh(z2);
            float og = fsigm(z3);
            c_reg = fg * c_reg + ig * gg;
            float hv = ftanh(c_reg) * og;
            hdst[o_n * 32 + o_b] = hv;
            out[(size_t)o_b * (S_LEN * HID) + (size_t)s * HID + o_n] = hv;
        }
        grid_barrier(s);
    }
}

// ---------------- launch ----------------
extern "C" void kernel_launch(void* const* d_in, const int* in_sizes, int n_in,
                              void* d_out, int out_size) {
    const float* x    = (const float*)d_in[0];   // (32,2048,256)
    const float* h0   = (const float*)d_in[1];   // (1,32,256)
    const float* c0   = (const float*)d_in[2];   // (1,32,256)
    const float* W    = (const float*)d_in[3];   // (512,1024)
    const float* bias = (const float*)d_in[4];   // (1024,)
    float* out = (float*)d_out;                  // (32,2048,256) + 2*(1,32,256) zeros

    gemm_x_kernel<<<dim3(512, 8, 1), 256>>>(x, W, bias);
    init_kernel<<<16, 256>>>(h0, out);
    lstm_rec_kernel<<<GRID_REC, 256>>>(W, c0, out);
}

// round 4
// speedup vs baseline: 1.0190x; 1.0190x over previous
#include <cuda_runtime.h>
#include <cstdint>
#include <cstddef>

typedef unsigned long long ull;

#define S_LEN   2048
#define BATCH   32
#define HID     256
#define GRID_REC 128

// ---------------- device scratch (no allocations allowed) ----------------
__device__ float g_Xc[(size_t)65536 * 1024];   // [s][col][b] : 256 MB, x@Wx + b
__device__ float g_hbuf[2][BATCH * HID];       // k-PAIR layout: [k2][b][2], double buffered
__device__ unsigned g_bar_count;
__device__ unsigned g_bar_epoch;

// ---------------- activations (accurate fast paths) ----------------
__device__ __forceinline__ float fsigm(float x) {
    return 1.0f / (1.0f + __expf(-x));
}
__device__ __forceinline__ float ftanh(float x) {
    x = fminf(9.0f, fmaxf(-9.0f, x));
    float e = __expf(-2.0f * x);
    return __fdividef(1.0f - e, 1.0f + e);
}

// ---------------- packed fp32x2 helpers ----------------
__device__ __forceinline__ ull ffma2(ull a, ull b, ull c) {
    ull d;
    asm("fma.rn.f32x2 %0, %1, %2, %3;" : "=l"(d) : "l"(a), "l"(b), "l"(c));
    return d;
}
__device__ __forceinline__ float f2sum(ull v) {
    float lo = __uint_as_float((unsigned)(v & 0xffffffffull));
    float hi = __uint_as_float((unsigned)(v >> 32));
    return lo + hi;
}
__device__ __forceinline__ ull fpack(float lo, float hi) {
    return ((ull)__float_as_uint(hi) << 32) | (ull)__float_as_uint(lo);
}

// ---------------- phase 1: Xc[s][col][b] = x[b][s][:] @ W[:256][col] + bias[col] ----------------
// M = 65536 rows ordered r = s*32 + b ; N = 1024 ; K = 256
__global__ void __launch_bounds__(256) gemm_x_kernel(const float* __restrict__ x,
                                                     const float* __restrict__ W,
                                                     const float* __restrict__ bias) {
    __shared__ float As[8][132];   // k-major, padded (conflict-free)
    __shared__ float Bs[8][128];
    const int tid = threadIdx.x;
    const int rt = blockIdx.x, ct = blockIdx.y;

    const int a_ri = tid >> 1, a_kq = (tid & 1) << 2;
    const int row  = rt * 128 + a_ri;            // r = s*32 + b
    const float* a_src = x + (size_t)(row & 31) * (S_LEN * 256)
                           + (size_t)(row >> 5) * 256 + a_kq;
    const int b_kr = tid >> 5, b_c4 = (tid & 31) << 2;
    const float* b_src = W + (size_t)b_kr * 1024 + ct * 128 + b_c4;

    const int ry = tid >> 4, cx = tid & 15;
    float acc[8][8];
#pragma unroll
    for (int i = 0; i < 8; i++)
#pragma unroll
        for (int j = 0; j < 8; j++) acc[i][j] = 0.0f;

    for (int kb = 0; kb < 256; kb += 8) {
        float4 av = *(const float4*)(a_src + kb);
        float4 bv = *(const float4*)(b_src + (size_t)kb * 1024);
        __syncthreads();
        As[a_kq + 0][a_ri] = av.x;
        As[a_kq + 1][a_ri] = av.y;
        As[a_kq + 2][a_ri] = av.z;
        As[a_kq + 3][a_ri] = av.w;
        *(float4*)&Bs[b_kr][b_c4] = bv;
        __syncthreads();
#pragma unroll
        for (int k = 0; k < 8; k++) {
            float ar[8], br[8];
            *(float4*)(ar)     = *(const float4*)&As[k][ry * 8];
            *(float4*)(ar + 4) = *(const float4*)&As[k][ry * 8 + 4];
            *(float4*)(br)     = *(const float4*)&Bs[k][cx * 8];
            *(float4*)(br + 4) = *(const float4*)&Bs[k][cx * 8 + 4];
#pragma unroll
            for (int i = 0; i < 8; i++)
#pragma unroll
                for (int j = 0; j < 8; j++)
                    acc[i][j] = fmaf(ar[i], br[j], acc[i][j]);
        }
    }

    float bb[8];
#pragma unroll
    for (int j = 0; j < 8; j++) bb[j] = bias[ct * 128 + cx * 8 + j];

#pragma unroll
    for (int i = 0; i < 8; i++) {
        int r = rt * 128 + ry * 8 + i;
        size_t base = (size_t)(r >> 5) * 32768 + (size_t)(r & 31);
#pragma unroll
        for (int j = 0; j < 8; j++) {
            int col = ct * 128 + cx * 8 + j;
            g_Xc[base + (size_t)col * 32] = acc[i][j] + bb[j];
        }
    }
}

// ---------------- init: barrier reset, h0 transpose into k-pair layout, zero output tail ----------------
__global__ void init_kernel(const float* __restrict__ h0, float* __restrict__ out) {
    int t = blockIdx.x * blockDim.x + threadIdx.x;   // 16*256 = 4096 threads
    if (t == 0) { g_bar_count = 0; g_bar_epoch = 0; }
    for (int idx = t; idx < BATCH * HID; idx += 4096) {
        int k = idx >> 5, b = idx & 31;
        // layout: [k2][b][2] with k2 = k>>1
        g_hbuf[0][(k >> 1) * 64 + b * 2 + (k & 1)] = h0[b * HID + k];
    }
    float* tail = out + (size_t)BATCH * S_LEN * HID;            // the two zero tensors
    for (int idx = t; idx < 2 * BATCH * HID; idx += 4096) tail[idx] = 0.0f;
}

// ---------------- grid-wide barrier: release/acquire, no MEMBAR.GPU ----------------
__device__ __forceinline__ void grid_barrier(int step) {
    __syncthreads();
    if (threadIdx.x == 0) {
        unsigned old;
        asm volatile("atom.add.acq_rel.gpu.global.u32 %0, [%1], 1;"
                     : "=r"(old) : "l"(&g_bar_count) : "memory");
        unsigned target = (unsigned)GRID_REC * (unsigned)(step + 1);
        if (old + 1u == target) {
            asm volatile("st.release.gpu.global.u32 [%0], %1;"
                         :: "l"(&g_bar_epoch), "r"((unsigned)(step + 1)) : "memory");
        } else {
            unsigned e;
            do {
                asm volatile("ld.acquire.gpu.global.u32 %0, [%1];"
                             : "=r"(e) : "l"(&g_bar_epoch) : "memory");
            } while (e < (unsigned)(step + 1));
        }
    }
    __syncthreads();
}

// ---------------- phase 2: persistent recurrence ----------------
// CTA cb owns hidden units n in {2cb, 2cb+1} for all 32 batches.
// Dot-product: thread t: b = t&31, slot = t>>5 -> (nl = slot&1, ks = slot>>1), kseg = 64 k (32 k-pairs).
// f32x2 FFMA2 over k-pairs; smem reduce; stage-2: all 256 threads assemble z + activations;
// stage-3: 64 owner threads update c,h.
__global__ void __launch_bounds__(256, 1) lstm_rec_kernel(const float* __restrict__ W,
                                                          const float* __restrict__ c0,
                                                          float* __restrict__ out) {
    __shared__ ull  h2s[128 * 32];         // h, k-pair layout [k2][b] as f32x2 : 32 KB
    __shared__ ull  Wsh2[8 * 128];         // [ (nl*4+g) ][k2] as f32x2 : 8 KB (weight-stationary)
    __shared__ float red[4][2][4][32];     // [ks][nl][gate][b]  4 KB
    __shared__ float act_s[2][4][32];      // [nl][gate][b]      1 KB

    const int tid = threadIdx.x;
    const int cb = blockIdx.x;
    const int n_base = cb * 2;

    // one-time Wh load: Wsh2[nl*4+g][k2] = (W[256+2k2][col], W[256+2k2+1][col])
    for (int idx = tid; idx < 1024; idx += 256) {
        int cl = idx >> 7, k2 = idx & 127;
        int col = (cl & 3) * 256 + n_base + (cl >> 2);
        float wlo = W[(size_t)(256 + 2 * k2) * 1024 + col];
        float whi = W[(size_t)(257 + 2 * k2) * 1024 + col];
        Wsh2[cl * 128 + k2] = fpack(wlo, whi);
    }

    // dot-product mapping
    const int b    = tid & 31;
    const int slot = tid >> 5;
    const int nl   = slot & 1;
    const int ks   = slot >> 1;       // 0..3, kseg of 32 k-pairs

    // stage-2 mapping: one (nl2, g2, b2) per thread
    const int b2  = tid & 31;
    const int nl2 = (tid >> 5) & 1;
    const int g2  = tid >> 6;
    const int xcol = g2 * 256 + n_base + nl2;

    // owner mapping (c/h update): 64 threads = 2 nl x 32 b
    const bool owner = (tid < 64);
    const int o_b  = tid & 31;
    const int o_nl = (tid >> 5) & 1;
    const int o_n  = n_base + o_nl;
    float c_reg = 0.0f;
    if (owner) c_reg = c0[o_b * HID + o_n];

    const ull* hseg = h2s + (ks * 32) * 32 + b;
    const ulonglong2* w0p = (const ulonglong2*)(Wsh2 + (nl * 4 + 0) * 128 + ks * 32);
    const ulonglong2* w1p = (const ulonglong2*)(Wsh2 + (nl * 4 + 1) * 128 + ks * 32);
    const ulonglong2* w2p = (const ulonglong2*)(Wsh2 + (nl * 4 + 2) * 128 + ks * 32);
    const ulonglong2* w3p = (const ulonglong2*)(Wsh2 + (nl * 4 + 3) * 128 + ks * 32);

    // prefetch Xc for step 0
    float xc_cur = g_Xc[(size_t)xcol * 32 + b2];
    __syncthreads();

    for (int s = 0; s < S_LEN; s++) {
        // load h into smem (coalesced float4 copy; layouts identical)
        {
            float4* d4 = (float4*)h2s;
            const float4* s4 = (const float4*)g_hbuf[s & 1];
#pragma unroll
            for (int j = 0; j < 8; j++) d4[tid + 256 * j] = s4[tid + 256 * j];
        }
        __syncthreads();

        // 4 gate dot-products over this thread's 32 k-pairs (FFMA2)
        ull a0 = 0ull, a1 = 0ull, a2 = 0ull, a3 = 0ull;
#pragma unroll
        for (int j = 0; j < 16; j++) {
            ull hA = hseg[(2 * j) * 32];        // LDS.64, conflict-free
            ull hB = hseg[(2 * j + 1) * 32];
            ulonglong2 w0 = w0p[j];             // LDS.128 broadcast
            ulonglong2 w1 = w1p[j];
            ulonglong2 w2 = w2p[j];
            ulonglong2 w3 = w3p[j];
            a0 = ffma2(hA, w0.x, a0); a0 = ffma2(hB, w0.y, a0);
            a1 = ffma2(hA, w1.x, a1); a1 = ffma2(hB, w1.y, a1);
            a2 = ffma2(hA, w2.x, a2); a2 = ffma2(hB, w2.y, a2);
            a3 = ffma2(hA, w3.x, a3); a3 = ffma2(hB, w3.y, a3);
        }
        red[ks][nl][0][b] = f2sum(a0);
        red[ks][nl][1][b] = f2sum(a1);
        red[ks][nl][2][b] = f2sum(a2);
        red[ks][nl][3][b] = f2sum(a3);
        __syncthreads();

        // stage 2: every thread assembles one z and applies activations
        {
            float z = red[0][nl2][g2][b2] + red[1][nl2][g2][b2]
                    + red[2][nl2][g2][b2] + red[3][nl2][g2][b2] + xc_cur;
            z = ftanh(z);                                    // reference quirk: tanh first
            float a = (g2 == 2) ? ftanh(z) : fsigm(z);
            act_s[nl2][g2][b2] = a;
        }
        __syncthreads();

        // stage 3: owners update cell + hidden
        if (owner) {
            float iv = act_s[o_nl][0][o_b];
            float fv = act_s[o_nl][1][o_b];
            float gv = act_s[o_nl][2][o_b];
            float ov = act_s[o_nl][3][o_b];
            c_reg = fv * c_reg + iv * gv;
            float hv = ftanh(c_reg) * ov;
            g_hbuf[(s & 1) ^ 1][cb * 64 + o_b * 2 + o_nl] = hv;   // k-pair layout
            out[(size_t)o_b * (S_LEN * HID) + (size_t)s * HID + o_n] = hv;
        }

        // prefetch next step's Xc BEFORE the barrier (DRAM latency hidden under the wait)
        if (s + 1 < S_LEN)
            xc_cur = g_Xc[(size_t)(s + 1) * 32768 + (size_t)xcol * 32 + b2];

        grid_barrier(s);
    }
}

// ---------------- launch ----------------
extern "C" void kernel_launch(void* const* d_in, const int* in_sizes, int n_in,
                              void* d_out, int out_size) {
    const float* x    = (const float*)d_in[0];   // (32,2048,256)
    const float* h0   = (const float*)d_in[1];   // (1,32,256)
    const float* c0   = (const float*)d_in[2];   // (1,32,256)
    const float* W    = (const float*)d_in[3];   // (512,1024)
    const float* bias = (const float*)d_in[4];   // (1024,)
    float* out = (float*)d_out;                  // (32,2048,256) + 2*(1,32,256) zeros

    gemm_x_kernel<<<dim3(512, 8, 1), 256>>>(x, W, bias);
    init_kernel<<<16, 256>>>(h0, out);
    lstm_rec_kernel<<<GRID_REC, 256>>>(W, c0, out);
}